// round 5
// baseline (speedup 1.0000x reference)
#include <cuda_runtime.h>

// Problem constants
#define BB 8
#define SS 4096
#define AA 3
#define KK 64
#define MARGIN 5.0f
#define ROWS (BB * SS)          // 32768
#define FLATN (SS * AA)         // 12288 per batch

// Output layout (float32):
//   [0] loss | [1..) predict_label (B,S,A) | total_idx (B*K,3) | candidate_label (B*K)
#define OFF_PRED 1
#define OFF_TI   (1 + ROWS * AA)            // 98305
#define OFF_CAND (OFF_TI + BB * KK * 3)     // 99841

#define NBLK 444    // 148 SMs x 3 blocks -> exactly one wave
#define MAXR 74     // 32768 = 356*74 + 88*73

// Scratch (static device globals -- no allocations allowed)
__device__ float g_logits[ROWS * 6];     // full logits (768 KB)
__device__ int   g_selflat[BB * KK];     // selected flat indices
__device__ int   g_ctr;                  // completion counter (reset each run)

// ---------------------------------------------------------------------------
// Single fused kernel.
//  Phase A (blocks 436..443 only): per-batch selection. Positives are forced
//    to exactly 2.0 (> any sigmoid < 1) and jax top_k is stable => select the
//    first 64 flat positions (ascending) with label==1. Labels are INT32
//    (jax x64 disabled). Emits total_idx + g_selflat. Independent of GEMM.
//  Phase B (all blocks): X(32768x1024) @ W(1024x6) + bias -> logits +
//    predict_label. 256 threads, thread t owns d=4t..4t+3 (24 W regs),
//    4 rows of loads batched per iteration (MLP>=4). Warp folds 6 accs via
//    18 SHFLs; 8 warp-partials combined in smem. Deterministic.
//  Phase C (last block to finish): candidate_label + margin loss (fixed
//    summation order => deterministic).
// ---------------------------------------------------------------------------
__global__ void __launch_bounds__(256, 3)
k_fused(const float* __restrict__ X, const float* __restrict__ W,
        const float* __restrict__ bias, const int* __restrict__ labels,
        float* __restrict__ out)
{
    __shared__ float sPart[MAXR * 48];   // [row][warp*6 + k]
    __shared__ float sFin[MAXR * 6];
    __shared__ int   s_idx[KK];
    __shared__ int   s_cnt[8];
    __shared__ float s_red[8];
    __shared__ int   s_flag;

    const int t    = threadIdx.x;        // 0..255
    const int warp = t >> 5;
    const int lane = t & 31;
    const int bid  = blockIdx.x;

    // ---------------- Phase A: selection (blocks 436..443) ----------------
    if (bid >= NBLK - BB) {
        const int b = bid - (NBLK - BB);
        const int* lab = labels + (size_t)b * FLATN;

        int found = 0;  // uniform across threads
        for (int base = 0; base < FLATN && found < KK; base += 256) {
            const int v = (lab[base + t] == 1);
            const unsigned m = __ballot_sync(0xffffffffu, v);
            if (lane == 0) s_cnt[warp] = __popc(m);
            __syncthreads();

            int wbase = found;
            for (int w = 0; w < warp; w++) wbase += s_cnt[w];
            const int g = wbase + __popc(m & ((1u << lane) - 1u));
            if (v && g < KK) s_idx[g] = base + t;

            int tot = 0;
#pragma unroll
            for (int w = 0; w < 8; w++) tot += s_cnt[w];
            found += tot;
            __syncthreads();
        }
        if (t < KK) {
            const int flat = s_idx[t];
            const int s = flat / AA;
            const int a = flat - s * AA;
            const size_t samp = (size_t)b * KK + t;
            g_selflat[samp] = flat;
            out[OFF_TI + samp * 3 + 0] = (float)b;
            out[OFF_TI + samp * 3 + 1] = (float)s;
            out[OFF_TI + samp * 3 + 2] = (float)a;
        }
        __syncthreads();   // smem reused below
    }

    // ---------------- Phase B: GEMM + logits + predict_label ----------------
    const int start = bid * 73 + min(bid, 356);
    const int nrows = 73 + (bid < 356 ? 1 : 0);

    // w[j*6+k] = W[(4t+j)*6 + k]
    float w[24];
#pragma unroll
    for (int i = 0; i < 24; i++) w[i] = W[t * 24 + i];

    const float4* __restrict__ X4 = reinterpret_cast<const float4*>(X);

#define PROC(RR, XV)                                                          \
    {                                                                         \
        const float xv[4] = {(XV).x, (XV).y, (XV).z, (XV).w};                 \
        float acc[6];                                                         \
        _Pragma("unroll") for (int k = 0; k < 6; k++) acc[k] = 0.0f;          \
        _Pragma("unroll") for (int j = 0; j < 4; j++)                         \
            _Pragma("unroll") for (int k = 0; k < 6; k++)                     \
                acc[k] = fmaf(xv[j], w[j * 6 + k], acc[k]);                   \
        float o[6];                                                           \
        _Pragma("unroll") for (int k = 0; k < 6; k++)                         \
            o[k] = __shfl_xor_sync(0xffffffffu, acc[k], 16);                  \
        float r0, r1, r2;                                                     \
        if (lane < 16) { r0 = acc[0]+o[0]; r1 = acc[1]+o[1]; r2 = acc[2]+o[2]; } \
        else           { r0 = acc[3]+o[3]; r1 = acc[4]+o[4]; r2 = acc[5]+o[5]; } \
        _Pragma("unroll") for (int off = 8; off > 0; off >>= 1) {             \
            r0 += __shfl_xor_sync(0xffffffffu, r0, off);                      \
            r1 += __shfl_xor_sync(0xffffffffu, r1, off);                      \
            r2 += __shfl_xor_sync(0xffffffffu, r2, off);                      \
        }                                                                     \
        if (lane == 0) {                                                      \
            sPart[(RR) * 48 + warp * 6 + 0] = r0;                             \
            sPart[(RR) * 48 + warp * 6 + 1] = r1;                             \
            sPart[(RR) * 48 + warp * 6 + 2] = r2;                             \
        }                                                                     \
        if (lane == 16) {                                                     \
            sPart[(RR) * 48 + warp * 6 + 3] = r0;                             \
            sPart[(RR) * 48 + warp * 6 + 4] = r1;                             \
            sPart[(RR) * 48 + warp * 6 + 5] = r2;                             \
        }                                                                     \
    }

    int r = 0;
    for (; r + 4 <= nrows; r += 4) {
        // batch 4 row-loads up front => MLP 4 per thread
        const float4 x0 = __ldg(&X4[(size_t)(start + r + 0) * 256 + t]);
        const float4 x1 = __ldg(&X4[(size_t)(start + r + 1) * 256 + t]);
        const float4 x2 = __ldg(&X4[(size_t)(start + r + 2) * 256 + t]);
        const float4 x3 = __ldg(&X4[(size_t)(start + r + 3) * 256 + t]);
        PROC(r + 0, x0)
        PROC(r + 1, x1)
        PROC(r + 2, x2)
        PROC(r + 3, x3)
    }
    for (; r < nrows; r++) {
        const float4 x0 = __ldg(&X4[(size_t)(start + r) * 256 + t]);
        PROC(r, x0)
    }
#undef PROC
    __syncthreads();

    // Cross-warp combine + bias; write logits and keep in smem.
    for (int v = t; v < nrows * 6; v += 256) {
        const int row = v / 6;
        const int k   = v - row * 6;
        float s = __ldg(&bias[k]);
#pragma unroll
        for (int w8 = 0; w8 < 8; w8++) s += sPart[row * 48 + w8 * 6 + k];
        g_logits[(size_t)(start + row) * 6 + k] = s;
        sFin[v] = s;
    }
    __syncthreads();

    // predict_label: argmax over C=2, first-max tie-break => 1 iff p1 > p0.
    for (int u = t; u < nrows * 3; u += 256) {
        const int row = u / 3;
        const int a   = u - row * 3;
        out[OFF_PRED + (size_t)(start + row) * 3 + a] =
            (sFin[row * 6 + 2 * a + 1] > sFin[row * 6 + 2 * a]) ? 1.0f : 0.0f;
    }

    // ---------------- Phase C: last block computes loss + candidate ----------
    __threadfence();
    if (t == 0) s_flag = (atomicAdd(&g_ctr, 1) == NBLK - 1) ? 1 : 0;
    __syncthreads();
    if (!s_flag) return;
    __threadfence();   // acquire: all blocks' logits/selflat visible

    float term = 0.0f;
#pragma unroll
    for (int i = 0; i < 2; i++) {
        const int samp = t + i * 256;                 // 512 samples total
        const int flat = g_selflat[samp];
        const int b2 = samp >> 6;                     // samp / KK
        const int s2 = flat / AA;
        const int a2 = flat - s2 * AA;
        const int row = b2 * SS + s2;
        const float p0 = g_logits[(size_t)row * 6 + 2 * a2];
        const float p1 = g_logits[(size_t)row * 6 + 2 * a2 + 1];
        out[OFF_CAND + samp] = (p1 > p0) ? 1.0f : 0.0f;
        // selected positions always have label 1 => y = 1; C = 2
        term += fmaxf(0.0f, MARGIN - p1 + p0) * 0.5f;
    }
#pragma unroll
    for (int off = 16; off > 0; off >>= 1)
        term += __shfl_xor_sync(0xffffffffu, term, off);
    if (lane == 0) s_red[warp] = term;
    __syncthreads();
    if (t == 0) {
        float tot = 0.0f;
#pragma unroll
        for (int w8 = 0; w8 < 8; w8++) tot += s_red[w8];
        out[0] = tot / (float)(BB * KK);
        g_ctr = 0;   // ready for next graph replay
    }
}

// ---------------------------------------------------------------------------
extern "C" void kernel_launch(void* const* d_in, const int* in_sizes, int n_in,
                              void* d_out, int out_size)
{
    const float* X      = (const float*)d_in[0];    // (B,S,D) f32
    const float* W      = (const float*)d_in[1];    // (D, A*C) f32
    const float* bias   = (const float*)d_in[2];    // (A*C,) f32
    const int*   labels = (const int*)d_in[3];      // (B,S,A) int32 (jax x64 off)
    float*       out    = (float*)d_out;

    k_fused<<<NBLK, 256>>>(X, W, bias, labels, out);
}

// round 8
// speedup vs baseline: 1.0435x; 1.0435x over previous
#include <cuda_runtime.h>

// Problem constants
#define BB 8
#define SS 4096
#define AA 3
#define KK 64
#define MARGIN 5.0f
#define ROWS (BB * SS)          // 32768
#define FLATN (SS * AA)         // 12288 per batch

// Output layout (float32):
//   [0] loss | [1..) predict_label (B,S,A) | total_idx (B*K,3) | candidate_label (B*K)
#define OFF_PRED 1
#define OFF_TI   (1 + ROWS * AA)            // 98305
#define OFF_CAND (OFF_TI + BB * KK * 3)     // 99841

#define NBLK 444    // 148 SMs x 3 blocks -> exactly one wave
#define MAXR 37     // teams 0..799 take 37 rows, 800..887 take 36

// Scratch (static device globals -- no allocations allowed)
__device__ float g_logits[ROWS * 6];     // full logits (768 KB)
__device__ int   g_selflat[BB * KK];     // selected flat indices
__device__ int   g_ctr;                  // completion counter (reset each run)

// ---------------------------------------------------------------------------
// Single fused kernel, 128 threads (4 warps) per block, occ 3 (<=168 regs).
//  Phase A (blocks 436..443): per-batch selection. Positives are forced to
//    exactly 2.0 (> any sigmoid < 1) and jax top_k is stable => select the
//    first 64 flat positions (ascending) with label==1. Labels are INT32.
//  Phase B (all blocks): X @ W + bias -> logits + predict_label.
//    TWO warps per row-team; lane owns 16 d's:
//      d = jq*256 + wu*128 + lane*4 + jj   (jq=0..3, jj=0..3)
//    (same decomposition for X and W!). 96 W regs. Per row: 96 FMA/lane +
//    18-SHFL folded butterfly per warp; 2 warp partials combined in smem.
//    Next-row loads software-pipelined (clamped index).
//  Phase C (last block to finish): candidate_label + margin loss (fixed
//    summation order => deterministic).
// ---------------------------------------------------------------------------
__global__ void __launch_bounds__(128, 3)
k_fused(const float* __restrict__ X, const float* __restrict__ W,
        const float* __restrict__ bias, const int* __restrict__ labels,
        float* __restrict__ out)
{
    __shared__ float sPart[2 * MAXR * 2 * 6];   // [team][row][warp-in-team][k]
    __shared__ float sFin[2 * MAXR * 6];        // [team][row][k]
    __shared__ int   s_idx[KK];
    __shared__ int   s_cnt[4];
    __shared__ float s_red[4];
    __shared__ int   s_flag;

    const int t    = threadIdx.x;        // 0..127
    const int warp = t >> 5;
    const int lane = t & 31;
    const int bid  = blockIdx.x;

    // ---------------- Phase A: selection (blocks 436..443) ----------------
    if (bid >= NBLK - BB) {
        const int b = bid - (NBLK - BB);
        const int* lab = labels + (size_t)b * FLATN;

        int found = 0;  // uniform across threads
        for (int base = 0; base < FLATN && found < KK; base += 128) {
            const int v = (lab[base + t] == 1);
            const unsigned m = __ballot_sync(0xffffffffu, v);
            if (lane == 0) s_cnt[warp] = __popc(m);
            __syncthreads();

            int wbase = found;
            for (int w = 0; w < warp; w++) wbase += s_cnt[w];
            const int g = wbase + __popc(m & ((1u << lane) - 1u));
            if (v && g < KK) s_idx[g] = base + t;

            int tot = 0;
#pragma unroll
            for (int w = 0; w < 4; w++) tot += s_cnt[w];
            found += tot;
            __syncthreads();
        }
        if (t < KK) {
            const int flat = s_idx[t];
            const int s = flat / AA;
            const int a = flat - s * AA;
            const size_t samp = (size_t)b * KK + t;
            g_selflat[samp] = flat;
            out[OFF_TI + samp * 3 + 0] = (float)b;
            out[OFF_TI + samp * 3 + 1] = (float)s;
            out[OFF_TI + samp * 3 + 2] = (float)a;
        }
        __syncthreads();   // smem reused below
    }

    // ---------------- Phase B: GEMM + logits + predict_label ----------------
    const int tw   = warp >> 1;              // team within block (0,1)
    const int wu   = warp & 1;               // warp within team
    const int team = bid * 2 + tw;           // 0..887
    const int start = team * 36 + min(team, 800);
    const int nr    = 36 + (team < 800 ? 1 : 0);   // same for both teams of a block

    // 96 W coefficients; lane owns d = jq*256 + wu*128 + lane*4 + jj
    // -- EXACTLY the same decomposition used for the X float4 loads below.
    float wR[96];
#pragma unroll
    for (int jq = 0; jq < 4; jq++)
#pragma unroll
        for (int jj = 0; jj < 4; jj++)
#pragma unroll
            for (int k = 0; k < 6; k++)
                wR[jq * 24 + jj * 6 + k] =
                    W[(jq * 256 + wu * 128 + lane * 4 + jj) * 6 + k];

    const float4* __restrict__ X4 = reinterpret_cast<const float4*>(X);
    const size_t fbase = (size_t)wu * 32 + lane;   // float4 idx: d/4 = jq*64 + wu*32 + lane

    // software pipeline: prefetch next row (clamped) while computing current
    float4 c0, c1, c2, c3;
    {
        const size_t rb = (size_t)start * 256;
        c0 = __ldg(&X4[rb + fbase +   0]);
        c1 = __ldg(&X4[rb + fbase +  64]);
        c2 = __ldg(&X4[rb + fbase + 128]);
        c3 = __ldg(&X4[rb + fbase + 192]);
    }

    for (int r = 0; r < nr; r++) {
        const int rn = (r + 1 < nr) ? (r + 1) : r;      // clamp: no OOB, no uninit
        const size_t rb = (size_t)(start + rn) * 256;
        const float4 n0 = __ldg(&X4[rb + fbase +   0]);
        const float4 n1 = __ldg(&X4[rb + fbase +  64]);
        const float4 n2 = __ldg(&X4[rb + fbase + 128]);
        const float4 n3 = __ldg(&X4[rb + fbase + 192]);

        const float xv[16] = {c0.x, c0.y, c0.z, c0.w,  c1.x, c1.y, c1.z, c1.w,
                              c2.x, c2.y, c2.z, c2.w,  c3.x, c3.y, c3.z, c3.w};
        float acc[6];
#pragma unroll
        for (int k = 0; k < 6; k++) acc[k] = 0.0f;
#pragma unroll
        for (int j = 0; j < 16; j++)
#pragma unroll
            for (int k = 0; k < 6; k++)
                acc[k] = fmaf(xv[j], wR[j * 6 + k], acc[k]);

        // 18-SHFL folded butterfly: stage 16 folds 6 accs -> 3 per half-warp.
        float o[6];
#pragma unroll
        for (int k = 0; k < 6; k++) o[k] = __shfl_xor_sync(0xffffffffu, acc[k], 16);
        float q0, q1, q2;
        if (lane < 16) { q0 = acc[0] + o[0]; q1 = acc[1] + o[1]; q2 = acc[2] + o[2]; }
        else           { q0 = acc[3] + o[3]; q1 = acc[4] + o[4]; q2 = acc[5] + o[5]; }
#pragma unroll
        for (int off = 8; off > 0; off >>= 1) {
            q0 += __shfl_xor_sync(0xffffffffu, q0, off);
            q1 += __shfl_xor_sync(0xffffffffu, q1, off);
            q2 += __shfl_xor_sync(0xffffffffu, q2, off);
        }
        // lane 0: totals k=0..2 of this warp's 512 d's; lane 16: k=3..5.
        float* dst = &sPart[((tw * MAXR + r) * 2 + wu) * 6];
        if (lane == 0)  { dst[0] = q0; dst[1] = q1; dst[2] = q2; }
        if (lane == 16) { dst[3] = q0; dst[4] = q1; dst[5] = q2; }

        c0 = n0; c1 = n1; c2 = n2; c3 = n3;
    }
    __syncthreads();

    // Cross-warp (2 partials) combine + bias; write logits, keep in smem.
    for (int v = t; v < 2 * nr * 6; v += 128) {
        const int tw2 = v / (nr * 6);
        const int rem = v - tw2 * nr * 6;
        const int row = rem / 6;
        const int k   = rem - row * 6;
        const int team2 = bid * 2 + tw2;
        const int st2   = team2 * 36 + min(team2, 800);
        float s = __ldg(&bias[k])
                + sPart[((tw2 * MAXR + row) * 2 + 0) * 6 + k]
                + sPart[((tw2 * MAXR + row) * 2 + 1) * 6 + k];
        g_logits[(size_t)(st2 + row) * 6 + k] = s;
        sFin[(tw2 * MAXR + row) * 6 + k] = s;
    }
    __syncthreads();

    // predict_label: argmax over C=2, first-max tie-break => 1 iff p1 > p0.
    for (int u = t; u < 2 * nr * 3; u += 128) {
        const int tw2 = u / (nr * 3);
        const int rem = u - tw2 * nr * 3;
        const int row = rem / 3;
        const int a   = rem - row * 3;
        const int team2 = bid * 2 + tw2;
        const int st2   = team2 * 36 + min(team2, 800);
        out[OFF_PRED + (size_t)(st2 + row) * 3 + a] =
            (sFin[(tw2 * MAXR + row) * 6 + 2 * a + 1] >
             sFin[(tw2 * MAXR + row) * 6 + 2 * a]) ? 1.0f : 0.0f;
    }

    // ---------------- Phase C: last block computes loss + candidate ----------
    __threadfence();
    if (t == 0) s_flag = (atomicAdd(&g_ctr, 1) == NBLK - 1) ? 1 : 0;
    __syncthreads();
    if (!s_flag) return;
    __threadfence();   // acquire: all blocks' logits/selflat visible

    float term = 0.0f;
#pragma unroll
    for (int i = 0; i < 4; i++) {
        const int samp = t + i * 128;                 // 512 samples total
        const int flat = g_selflat[samp];
        const int b2 = samp >> 6;                     // samp / KK
        const int s2 = flat / AA;
        const int a2 = flat - s2 * AA;
        const int row = b2 * SS + s2;
        const float p0 = g_logits[(size_t)row * 6 + 2 * a2];
        const float p1 = g_logits[(size_t)row * 6 + 2 * a2 + 1];
        out[OFF_CAND + samp] = (p1 > p0) ? 1.0f : 0.0f;
        // selected positions always have label 1 => y = 1; C = 2
        term += fmaxf(0.0f, MARGIN - p1 + p0) * 0.5f;
    }
#pragma unroll
    for (int off = 16; off > 0; off >>= 1)
        term += __shfl_xor_sync(0xffffffffu, term, off);
    if (lane == 0) s_red[warp] = term;
    __syncthreads();
    if (t == 0) {
        float tot = 0.0f;
#pragma unroll
        for (int w = 0; w < 4; w++) tot += s_red[w];
        out[0] = tot / (float)(BB * KK);
        g_ctr = 0;   // ready for next graph replay
    }
}

// ---------------------------------------------------------------------------
extern "C" void kernel_launch(void* const* d_in, const int* in_sizes, int n_in,
                              void* d_out, int out_size)
{
    const float* X      = (const float*)d_in[0];    // (B,S,D) f32
    const float* W      = (const float*)d_in[1];    // (D, A*C) f32
    const float* bias   = (const float*)d_in[2];    // (A*C,) f32
    const int*   labels = (const int*)d_in[3];      // (B,S,A) int32 (jax x64 off)
    float*       out    = (float*)d_out;

    k_fused<<<NBLK, 128>>>(X, W, bias, labels, out);
}

// round 9
// speedup vs baseline: 1.3322x; 1.2767x over previous
#include <cuda_runtime.h>
#include <cstdint>

// Problem constants
#define BB 8
#define SS 4096
#define AA 3
#define KK 64
#define MARGIN 5.0f
#define ROWS (BB * SS)          // 32768
#define FLATN (SS * AA)         // 12288 per batch

// Output layout (float32):
//   [0] loss | [1..) predict_label (B,S,A) | total_idx (B*K,3) | candidate_label (B*K)
#define OFF_PRED 1
#define OFF_TI   (1 + ROWS * AA)            // 98305
#define OFF_CAND (OFF_TI + BB * KK * 3)     // 99841

#define NBLK 444    // 148 SMs x 3 blocks -> exactly one wave
#define MAXR 37     // teams 0..799 take 37 rows, 800..887 take 36
#define DEPTH 8     // cp.async pipeline depth (rows per team in flight)
#define STAGE_BYTES (2 * DEPTH * 4096)   // 64 KB dynamic smem per block

// Scratch (static device globals -- no allocations allowed)
__device__ float g_logits[ROWS * 6];     // full logits (768 KB)
__device__ int   g_selflat[BB * KK];     // selected flat indices
__device__ int   g_ctr;                  // completion counter (reset each run)

__device__ __forceinline__ void cp16(uint32_t dst_smem, const void* src) {
    asm volatile("cp.async.cg.shared.global [%0], [%1], 16;"
                 :: "r"(dst_smem), "l"(src));
}
#define CP_COMMIT()  asm volatile("cp.async.commit_group;" ::: "memory")
#define CP_WAIT7()   asm volatile("cp.async.wait_group 7;" ::: "memory")

// ---------------------------------------------------------------------------
// Single fused kernel, 128 threads (4 warps), occ 3.
//  Phase A (blocks 436..443): per-batch selection. Positives forced to exactly
//    2.0 (> any sigmoid < 1), stable top_k => first 64 ascending flat positions
//    with label==1. Labels are INT32 (jax x64 off).
//  Phase B (all blocks): X @ W + bias -> logits + predict_label.
//    2 warps per row-team; lane owns d = jq*256 + wu*128 + lane*4 + jj (96 W
//    regs). X rows stream through an 8-deep cp.async smem ring; each thread
//    copies exactly the 4x16B chunks it later reads -> its own wait_group is
//    the only sync needed. 18-SHFL folded butterfly per warp; 2 warp partials
//    combined in smem. Deterministic.
//  Phase C (last block): candidate_label + margin loss (fixed order).
// ---------------------------------------------------------------------------
__global__ void __launch_bounds__(128, 3)
k_fused(const float* __restrict__ X, const float* __restrict__ W,
        const float* __restrict__ bias, const int* __restrict__ labels,
        float* __restrict__ out)
{
    extern __shared__ float4 stage[];           // [2][DEPTH][256] float4
    __shared__ float sPart[2 * MAXR * 2 * 6];   // [team][row][warp-in-team][k]
    __shared__ float sFin[2 * MAXR * 6];        // [team][row][k]
    __shared__ int   s_idx[KK];
    __shared__ int   s_cnt[4];
    __shared__ float s_red[4];
    __shared__ int   s_flag;

    const int t    = threadIdx.x;        // 0..127
    const int warp = t >> 5;
    const int lane = t & 31;
    const int bid  = blockIdx.x;

    // ---------------- Phase A: selection (blocks 436..443) ----------------
    if (bid >= NBLK - BB) {
        const int b = bid - (NBLK - BB);
        const int* lab = labels + (size_t)b * FLATN;

        int found = 0;  // uniform across threads
        for (int base = 0; base < FLATN && found < KK; base += 128) {
            const int v = (lab[base + t] == 1);
            const unsigned m = __ballot_sync(0xffffffffu, v);
            if (lane == 0) s_cnt[warp] = __popc(m);
            __syncthreads();

            int wbase = found;
            for (int w = 0; w < warp; w++) wbase += s_cnt[w];
            const int g = wbase + __popc(m & ((1u << lane) - 1u));
            if (v && g < KK) s_idx[g] = base + t;

            int tot = 0;
#pragma unroll
            for (int w = 0; w < 4; w++) tot += s_cnt[w];
            found += tot;
            __syncthreads();
        }
        if (t < KK) {
            const int flat = s_idx[t];
            const int s = flat / AA;
            const int a = flat - s * AA;
            const size_t samp = (size_t)b * KK + t;
            g_selflat[samp] = flat;
            out[OFF_TI + samp * 3 + 0] = (float)b;
            out[OFF_TI + samp * 3 + 1] = (float)s;
            out[OFF_TI + samp * 3 + 2] = (float)a;
        }
        __syncthreads();   // smem reused below
    }

    // ---------------- Phase B: GEMM + logits + predict_label ----------------
    const int tw   = warp >> 1;              // team within block (0,1)
    const int wu   = warp & 1;               // warp within team
    const int team = bid * 2 + tw;           // 0..887
    const int start = team * 36 + min(team, 800);
    const int nr    = 36 + (team < 800 ? 1 : 0);

    // 96 W coefficients; lane owns d = jq*256 + wu*128 + lane*4 + jj
    float wR[96];
#pragma unroll
    for (int jq = 0; jq < 4; jq++)
#pragma unroll
        for (int jj = 0; jj < 4; jj++)
#pragma unroll
            for (int k = 0; k < 6; k++)
                wR[jq * 24 + jj * 6 + k] =
                    W[(jq * 256 + wu * 128 + lane * 4 + jj) * 6 + k];

    const float4* __restrict__ X4 = reinterpret_cast<const float4*>(X);
    const int cf4 = wu * 32 + lane;          // this thread's f4 offset within a row-quarter

    uint32_t sbase;
    asm("{ .reg .u64 tt; cvta.to.shared.u64 tt, %1; cvt.u32.u64 %0, tt; }"
        : "=r"(sbase) : "l"(stage));
    const uint32_t my_db0 = sbase + (uint32_t)tw * (DEPTH * 4096)
                          + (uint32_t)wu * 512 + (uint32_t)lane * 16;

    // Preload DEPTH rows (one commit-group per row; uniform group count).
#pragma unroll
    for (int i = 0; i < DEPTH; i++) {
        // nr >= 36 > DEPTH, so all preload rows exist
        const float4* srow = X4 + (size_t)(start + i) * 256 + cf4;
        const uint32_t db = my_db0 + (uint32_t)i * 4096;
        cp16(db +    0, srow +   0);
        cp16(db + 1024, srow +  64);
        cp16(db + 2048, srow + 128);
        cp16(db + 3072, srow + 192);
        CP_COMMIT();
    }

    for (int r = 0; r < nr; r++) {
        CP_WAIT7();                              // oldest group (row r) resident
        const int slot = r & (DEPTH - 1);
        const float4* sl = stage + (tw * DEPTH + slot) * 256 + cf4;
        const float4 c0 = sl[0];
        const float4 c1 = sl[64];
        const float4 c2 = sl[128];
        const float4 c3 = sl[192];

        // Refill this slot with row r+DEPTH (data arrives >>29cyc after LDS).
        const int rf = r + DEPTH;
        if (rf < nr) {
            const float4* srow = X4 + (size_t)(start + rf) * 256 + cf4;
            const uint32_t db = my_db0 + (uint32_t)slot * 4096;
            cp16(db +    0, srow +   0);
            cp16(db + 1024, srow +  64);
            cp16(db + 2048, srow + 128);
            cp16(db + 3072, srow + 192);
        }
        CP_COMMIT();                             // (possibly empty) group; uniform count

        const float xv[16] = {c0.x, c0.y, c0.z, c0.w,  c1.x, c1.y, c1.z, c1.w,
                              c2.x, c2.y, c2.z, c2.w,  c3.x, c3.y, c3.z, c3.w};
        float acc[6];
#pragma unroll
        for (int k = 0; k < 6; k++) acc[k] = 0.0f;
#pragma unroll
        for (int j = 0; j < 16; j++)
#pragma unroll
            for (int k = 0; k < 6; k++)
                acc[k] = fmaf(xv[j], wR[j * 6 + k], acc[k]);

        // 18-SHFL folded butterfly: stage 16 folds 6 accs -> 3 per half-warp.
        float o[6];
#pragma unroll
        for (int k = 0; k < 6; k++) o[k] = __shfl_xor_sync(0xffffffffu, acc[k], 16);
        float q0, q1, q2;
        if (lane < 16) { q0 = acc[0] + o[0]; q1 = acc[1] + o[1]; q2 = acc[2] + o[2]; }
        else           { q0 = acc[3] + o[3]; q1 = acc[4] + o[4]; q2 = acc[5] + o[5]; }
#pragma unroll
        for (int off = 8; off > 0; off >>= 1) {
            q0 += __shfl_xor_sync(0xffffffffu, q0, off);
            q1 += __shfl_xor_sync(0xffffffffu, q1, off);
            q2 += __shfl_xor_sync(0xffffffffu, q2, off);
        }
        float* dst = &sPart[((tw * MAXR + r) * 2 + wu) * 6];
        if (lane == 0)  { dst[0] = q0; dst[1] = q1; dst[2] = q2; }
        if (lane == 16) { dst[3] = q0; dst[4] = q1; dst[5] = q2; }
    }
    __syncthreads();

    // Cross-warp (2 partials) combine + bias; write logits, keep in smem.
    for (int v = t; v < 2 * nr * 6; v += 128) {
        const int tw2 = v / (nr * 6);
        const int rem = v - tw2 * nr * 6;
        const int row = rem / 6;
        const int k   = rem - row * 6;
        const int team2 = bid * 2 + tw2;
        const int st2   = team2 * 36 + min(team2, 800);
        float s = __ldg(&bias[k])
                + sPart[((tw2 * MAXR + row) * 2 + 0) * 6 + k]
                + sPart[((tw2 * MAXR + row) * 2 + 1) * 6 + k];
        g_logits[(size_t)(st2 + row) * 6 + k] = s;
        sFin[(tw2 * MAXR + row) * 6 + k] = s;
    }
    __syncthreads();

    // predict_label: argmax over C=2, first-max tie-break => 1 iff p1 > p0.
    for (int u = t; u < 2 * nr * 3; u += 128) {
        const int tw2 = u / (nr * 3);
        const int rem = u - tw2 * nr * 3;
        const int row = rem / 3;
        const int a   = rem - row * 3;
        const int team2 = bid * 2 + tw2;
        const int st2   = team2 * 36 + min(team2, 800);
        out[OFF_PRED + (size_t)(st2 + row) * 3 + a] =
            (sFin[(tw2 * MAXR + row) * 6 + 2 * a + 1] >
             sFin[(tw2 * MAXR + row) * 6 + 2 * a]) ? 1.0f : 0.0f;
    }

    // ---------------- Phase C: last block computes loss + candidate ----------
    __threadfence();
    if (t == 0) s_flag = (atomicAdd(&g_ctr, 1) == NBLK - 1) ? 1 : 0;
    __syncthreads();
    if (!s_flag) return;
    __threadfence();   // acquire: all blocks' logits/selflat visible

    float term = 0.0f;
#pragma unroll
    for (int i = 0; i < 4; i++) {
        const int samp = t + i * 128;                 // 512 samples total
        const int flat = g_selflat[samp];
        const int b2 = samp >> 6;                     // samp / KK
        const int s2 = flat / AA;
        const int a2 = flat - s2 * AA;
        const int row = b2 * SS + s2;
        const float p0 = g_logits[(size_t)row * 6 + 2 * a2];
        const float p1 = g_logits[(size_t)row * 6 + 2 * a2 + 1];
        out[OFF_CAND + samp] = (p1 > p0) ? 1.0f : 0.0f;
        // selected positions always have label 1 => y = 1; C = 2
        term += fmaxf(0.0f, MARGIN - p1 + p0) * 0.5f;
    }
#pragma unroll
    for (int off = 16; off > 0; off >>= 1)
        term += __shfl_xor_sync(0xffffffffu, term, off);
    if (lane == 0) s_red[warp] = term;
    __syncthreads();
    if (t == 0) {
        float tot = 0.0f;
#pragma unroll
        for (int w = 0; w < 4; w++) tot += s_red[w];
        out[0] = tot / (float)(BB * KK);
        g_ctr = 0;   // ready for next graph replay
    }
}

// ---------------------------------------------------------------------------
extern "C" void kernel_launch(void* const* d_in, const int* in_sizes, int n_in,
                              void* d_out, int out_size)
{
    const float* X      = (const float*)d_in[0];    // (B,S,D) f32
    const float* W      = (const float*)d_in[1];    // (D, A*C) f32
    const float* bias   = (const float*)d_in[2];    // (A*C,) f32
    const int*   labels = (const int*)d_in[3];      // (B,S,A) int32 (jax x64 off)
    float*       out    = (float*)d_out;

    // Not an allocation; deterministic; capture-safe (no stream work enqueued).
    cudaFuncSetAttribute(k_fused, cudaFuncAttributeMaxDynamicSharedMemorySize,
                         STAGE_BYTES);
    k_fused<<<NBLK, 128, STAGE_BYTES>>>(X, W, bias, labels, out);
}